// round 8
// baseline (speedup 1.0000x reference)
#include <cuda_runtime.h>

// ---------------- problem constants ----------------
#define B_NODES   4096
#define DIM       128
#define S_SAMP    10
#define NUM_CELLS 2000
#define NUM_DRUGS 4000
#define NUM_GENES 20000

// ---------------- scratch (device globals; no allocation allowed) ----------------
__device__ float g_drug_proj[NUM_DRUGS * DIM];   //  2.0 MB
__device__ float g_gene_proj[NUM_GENES * DIM];   // 10.2 MB
__device__ float g_h[B_NODES * DIM];             //  2.0 MB
__device__ float g_agg[6 * B_NODES * DIM];       // 12.6 MB  [l*3+t][B][D]

// ---------------- f32x2 packed-FMA helpers (Blackwell) ----------------
__device__ __forceinline__ unsigned long long pack2(float x, float y) {
    unsigned long long r;
    asm("mov.b64 %0, {%1, %2};" : "=l"(r) : "f"(x), "f"(y));
    return r;
}
__device__ __forceinline__ void fma2(unsigned long long& d,
                                     unsigned long long a, unsigned long long b) {
    asm("fma.rn.f32x2 %0, %1, %2, %0;" : "+l"(d) : "l"(a), "l"(b));
}
__device__ __forceinline__ float2 unpack2(unsigned long long v) {
    float lo, hi;
    asm("mov.b64 {%0, %1}, %2;" : "=f"(lo), "=f"(hi) : "l"(v));
    return make_float2(lo, hi);
}

// ==================================================================
// Projection GEMM: out[M,128] = F[M,K] @ W[K,128] + bias
// BM=64, BN=128, BK=32, 128 threads, per-thread 8x8 (f32x2-paired cols)
// ==================================================================
template <int K>
__global__ __launch_bounds__(128) void proj_kernel(
    const float* __restrict__ F, const float* __restrict__ W,
    const float* __restrict__ bias, float* __restrict__ out, int M)
{
    __shared__ float As[64 * 33];     // padded pitch 33: conflict-free A reads
    __shared__ float Bs[32 * 128];

    const int tid  = threadIdx.x;
    const int tx   = tid & 15;        // 16 col-groups of 8
    const int ty   = tid >> 4;        // 8  row-groups of 8
    const int row0 = blockIdx.x * 64;

    unsigned long long acc[8][4];
#pragma unroll
    for (int i = 0; i < 8; i++)
#pragma unroll
        for (int j = 0; j < 4; j++) acc[i][j] = 0ull;

    for (int kt = 0; kt < K / 32; kt++) {
        // A tile 64x32 (guarded)
#pragma unroll
        for (int i = 0; i < 4; i++) {
            int f  = tid + i * 128;               // 0..511 float4s
            int r  = f >> 3;
            int c4 = f & 7;
            float4 v = make_float4(0.f, 0.f, 0.f, 0.f);
            if (row0 + r < M)
                v = *(const float4*)(F + (size_t)(row0 + r) * K + kt * 32 + c4 * 4);
            float* dst = As + r * 33 + c4 * 4;
            dst[0] = v.x; dst[1] = v.y; dst[2] = v.z; dst[3] = v.w;
        }
        // B tile 32x128 (contiguous rows of W)
        const float4* wsrc = (const float4*)(W + (size_t)kt * 32 * 128);
#pragma unroll
        for (int i = 0; i < 8; i++)
            ((float4*)Bs)[tid + i * 128] = wsrc[tid + i * 128];
        __syncthreads();

#pragma unroll 4
        for (int k = 0; k < 32; k++) {
            unsigned long long ap[8];
#pragma unroll
            for (int i = 0; i < 8; i++) {
                float a = As[(ty * 8 + i) * 33 + k];
                ap[i] = pack2(a, a);
            }
            const unsigned long long* bp =
                (const unsigned long long*)(Bs + k * 128 + tx * 8);
#pragma unroll
            for (int j = 0; j < 4; j++) {
                unsigned long long bv = bp[j];
#pragma unroll
                for (int i = 0; i < 8; i++) fma2(acc[i][j], ap[i], bv);
            }
        }
        __syncthreads();
    }

#pragma unroll
    for (int i = 0; i < 8; i++) {
        int row = row0 + ty * 8 + i;
        if (row < M) {
#pragma unroll
            for (int j = 0; j < 4; j++) {
                int c = tx * 8 + j * 2;
                float2 v = unpack2(acc[i][j]);
                v.x += bias[c];
                v.y += bias[c + 1];
                *(float2*)(out + (size_t)row * 128 + c) = v;
            }
        }
    }
}

// ==================================================================
// Center embedding gather: h[b] = drug_proj[center_ids[b]]
// ==================================================================
__global__ void gather_center(const float* __restrict__ drug_proj,
                              const int* __restrict__ ids,
                              float* __restrict__ h)
{
    int i = blockIdx.x * blockDim.x + threadIdx.x;  // float4 index
    if (i < B_NODES * 32) {
        int r = i >> 5;
        int c = i & 31;
        ((float4*)h)[i] =
            ((const float4*)(drug_proj + (size_t)ids[r] * 128))[c];
    }
}

// ==================================================================
// Fused RNN aggregation: one block = 64 B-rows of one (layer,type).
// Wx/Wh/bias resident in smem; H kept in smem across 10 steps;
// per-step neighbor gather into smem; f32x2 FMA, XOR-4 swizzle on
// X/H column index to avoid ty-half bank conflicts.
// grid = (64, 6); 128 threads.
// ==================================================================
__global__ __launch_bounds__(128) void rnn_kernel(
    const float* __restrict__ cell_tab,
    const int*   __restrict__ cell_neigh,
    const int*   __restrict__ drug_neigh,
    const int*   __restrict__ gene_neigh,
    const float* __restrict__ rnn_Wx,
    const float* __restrict__ rnn_Wh,
    const float* __restrict__ rnn_b)
{
    extern __shared__ float sm[];
    float* Wx  = sm;                    // 16384
    float* Wh  = sm + 16384;            // 16384
    float* bsh = sm + 32768;            // 128
    float* Hs  = sm + 32896;            // 64*132
    float* Xs  = Hs + 64 * 132;         // 64*132

    const int tid   = threadIdx.x;
    const int tx    = tid & 15;
    const int ty    = tid >> 4;
    const int lt    = blockIdx.y;       // 0..5 = layer*3 + type
    const int layer = lt / 3;
    const int t     = lt % 3;
    const int row0  = blockIdx.x * 64;

    const float* table;
    const int*   neigh;
    if (t == 0)      { table = cell_tab;    neigh = cell_neigh; }
    else if (t == 1) { table = g_drug_proj; neigh = drug_neigh; }
    else             { table = g_gene_proj; neigh = gene_neigh; }

    // resident weights + bias
    {
        const float4* wx4 = (const float4*)(rnn_Wx + (size_t)lt * 16384);
        const float4* wh4 = (const float4*)(rnn_Wh + (size_t)lt * 16384);
        float4* dWx = (float4*)Wx;
        float4* dWh = (float4*)Wh;
#pragma unroll
        for (int i = 0; i < 32; i++) {
            dWx[tid + i * 128] = wx4[tid + i * 128];
            dWh[tid + i * 128] = wh4[tid + i * 128];
        }
        bsh[tid] = rnn_b[lt * 128 + tid];
    }
    for (int i = tid; i < 64 * 132; i += 128) Hs[i] = 0.f;

    const int swz = (ty & 1) << 2;      // col-index XOR for this row group

    for (int s = 0; s < S_SAMP; s++) {
        __syncthreads();
        // gather X tile (swizzled by float4-block XOR)
#pragma unroll
        for (int i = 0; i < 16; i++) {
            int f  = tid + i * 128;             // 0..2047 float4s
            int r  = f >> 5;
            int c4 = f & 31;
            int b  = row0 + r;
            int nid = neigh[(layer * B_NODES + b) * S_SAMP + s];
            float4 v = *(const float4*)(table + (size_t)nid * 128 + c4 * 4);
            int c4s = c4 ^ ((r >> 3) & 1);
            *(float4*)(Xs + r * 132 + c4s * 4) = v;
        }
        __syncthreads();

        unsigned long long acc[8][4];
#pragma unroll
        for (int i = 0; i < 8; i++)
#pragma unroll
            for (int j = 0; j < 4; j++) acc[i][j] = 0ull;

#pragma unroll 2
        for (int k = 0; k < 128; k++) {
            int ks = k ^ swz;
            unsigned long long px[8], ph[8];
#pragma unroll
            for (int i = 0; i < 8; i++) {
                float xv = Xs[(ty * 8 + i) * 132 + ks];
                float hv = Hs[(ty * 8 + i) * 132 + ks];
                px[i] = pack2(xv, xv);
                ph[i] = pack2(hv, hv);
            }
            const unsigned long long* bx =
                (const unsigned long long*)(Wx + k * 128 + tx * 8);
            const unsigned long long* bh =
                (const unsigned long long*)(Wh + k * 128 + tx * 8);
#pragma unroll
            for (int j = 0; j < 4; j++) {
                unsigned long long wxv = bx[j];
                unsigned long long whv = bh[j];
#pragma unroll
                for (int i = 0; i < 8; i++) {
                    fma2(acc[i][j], px[i], wxv);
                    fma2(acc[i][j], ph[i], whv);
                }
            }
        }
        __syncthreads();

        // h = tanh(acc + b), write back swizzled
#pragma unroll
        for (int i = 0; i < 8; i++) {
            int r = ty * 8 + i;
#pragma unroll
            for (int j = 0; j < 4; j++) {
                int c = tx * 8 + j * 2;
                float2 v = unpack2(acc[i][j]);
                float h0 = tanhf(v.x + bsh[c]);
                float h1 = tanhf(v.y + bsh[c + 1]);
                int cs = c ^ swz;
                Hs[r * 132 + cs]     = h0;
                Hs[r * 132 + cs + 1] = h1;
            }
        }
    }
    __syncthreads();

    // write agg (de-swizzle)
    float* out = g_agg + ((size_t)lt * B_NODES + row0) * 128;
    for (int i = tid; i < 64 * 128; i += 128) {
        int r = i >> 7;
        int c = i & 127;
        int cs = c ^ (((r >> 3) & 1) << 2);
        out[(size_t)r * 128 + c] = Hs[r * 132 + cs];
    }
}

// ==================================================================
// Attention combine: warp per row. cands = [h, agg_cell, agg_drug, agg_gene]
// score_c = lrelu( dot(w[:128],h) + dot(w[128:],cand_c) ); softmax; combine.
// ==================================================================
__device__ __forceinline__ float warp_dot(float4 x, float4 y) {
    float v = x.x * y.x + x.y * y.y + x.z * y.z + x.w * y.w;
#pragma unroll
    for (int o = 16; o; o >>= 1) v += __shfl_xor_sync(0xffffffffu, v, o);
    return v;
}

__global__ void att_kernel(const float* __restrict__ hin,
                           const float* __restrict__ aggL,   // [3][B][128]
                           const float* __restrict__ attw,   // 256
                           float* __restrict__ out)
{
    int lane = threadIdx.x & 31;
    int w    = threadIdx.x >> 5;
    int row  = blockIdx.x * 4 + w;

    float4 hv = ((const float4*)(hin + (size_t)row * 128))[lane];
    float4 a0 = ((const float4*)(aggL + (size_t)row * 128))[lane];
    float4 a1 = ((const float4*)(aggL + (size_t)(B_NODES + row) * 128))[lane];
    float4 a2 = ((const float4*)(aggL + (size_t)(2 * B_NODES + row) * 128))[lane];
    float4 w1 = ((const float4*)attw)[lane];
    float4 w2 = ((const float4*)attw)[32 + lane];

    float ss = warp_dot(w1, hv);
    float sc[4];
    sc[0] = ss + warp_dot(w2, hv);
    sc[1] = ss + warp_dot(w2, a0);
    sc[2] = ss + warp_dot(w2, a1);
    sc[3] = ss + warp_dot(w2, a2);

#pragma unroll
    for (int c = 0; c < 4; c++)
        sc[c] = sc[c] > 0.f ? sc[c] : 0.01f * sc[c];   // leaky_relu(0.01)

    float m = fmaxf(fmaxf(sc[0], sc[1]), fmaxf(sc[2], sc[3]));
    float e0 = expf(sc[0] - m), e1 = expf(sc[1] - m);
    float e2 = expf(sc[2] - m), e3 = expf(sc[3] - m);
    float inv = 1.f / (e0 + e1 + e2 + e3);
    e0 *= inv; e1 *= inv; e2 *= inv; e3 *= inv;

    float4 o;
    o.x = e0 * hv.x + e1 * a0.x + e2 * a1.x + e3 * a2.x;
    o.y = e0 * hv.y + e1 * a0.y + e2 * a1.y + e3 * a2.y;
    o.z = e0 * hv.z + e1 * a0.z + e2 * a1.z + e3 * a2.z;
    o.w = e0 * hv.w + e1 * a0.w + e2 * a1.w + e3 * a2.w;
    ((float4*)(out + (size_t)row * 128))[lane] = o;
}

// ==================================================================
// Launch
// ==================================================================
extern "C" void kernel_launch(void* const* d_in, const int* in_sizes, int n_in,
                              void* d_out, int out_size)
{
    (void)in_sizes; (void)n_in; (void)out_size;

    const float* drug_feats = (const float*)d_in[0];
    const float* gene_feats = (const float*)d_in[1];
    const float* cell_tab   = (const float*)d_in[2];
    const float* W_drug     = (const float*)d_in[3];
    const float* b_drug     = (const float*)d_in[4];
    const float* W_gene     = (const float*)d_in[5];
    const float* b_gene     = (const float*)d_in[6];
    const float* rnn_Wx     = (const float*)d_in[7];
    const float* rnn_Wh     = (const float*)d_in[8];
    const float* rnn_b      = (const float*)d_in[9];
    const float* att_w      = (const float*)d_in[10];
    const int*   center_ids = (const int*)d_in[11];
    const int*   cell_neigh = (const int*)d_in[12];
    const int*   drug_neigh = (const int*)d_in[13];
    const int*   gene_neigh = (const int*)d_in[14];
    float*       out        = (float*)d_out;

    float *drug_proj, *gene_proj, *h, *agg;
    cudaGetSymbolAddress((void**)&drug_proj, g_drug_proj);
    cudaGetSymbolAddress((void**)&gene_proj, g_gene_proj);
    cudaGetSymbolAddress((void**)&h,         g_h);
    cudaGetSymbolAddress((void**)&agg,       g_agg);

    const size_t rnn_smem =
        (size_t)(16384 * 2 + 128 + 64 * 132 * 2) * sizeof(float);  // 199168 B
    cudaFuncSetAttribute(rnn_kernel,
                         cudaFuncAttributeMaxDynamicSharedMemorySize,
                         (int)rnn_smem);

    // 1) project full feature tables once (6x FLOP reduction vs per-sample)
    proj_kernel<1024><<<(NUM_DRUGS + 63) / 64, 128>>>(drug_feats, W_drug, b_drug,
                                                      drug_proj, NUM_DRUGS);
    proj_kernel<2048><<<(NUM_GENES + 63) / 64, 128>>>(gene_feats, W_gene, b_gene,
                                                      gene_proj, NUM_GENES);

    // 2) center embeddings
    gather_center<<<512, 256>>>(drug_proj, center_ids, h);

    // 3) all 6 (layer,type) RNN aggregations in one grid (h-independent)
    rnn_kernel<<<dim3(64, 6), 128, rnn_smem>>>(cell_tab, cell_neigh, drug_neigh,
                                               gene_neigh, rnn_Wx, rnn_Wh, rnn_b);

    // 4) attention combine per layer (layer 0 in-place on h, layer 1 -> out)
    att_kernel<<<B_NODES / 4, 128>>>(h, agg, att_w, h);
    att_kernel<<<B_NODES / 4, 128>>>(h, agg + (size_t)3 * B_NODES * DIM,
                                     att_w + 256, out);
}

// round 9
// speedup vs baseline: 1.0416x; 1.0416x over previous
#include <cuda_runtime.h>

// ---------------- problem constants ----------------
#define B_NODES   4096
#define DIM       128
#define S_SAMP    10
#define NUM_CELLS 2000
#define NUM_DRUGS 4000
#define NUM_GENES 20000

// ---------------- scratch (device globals; no allocation allowed) ----------------
__device__ float g_drug_proj[NUM_DRUGS * DIM];   //  2.0 MB
__device__ float g_gene_proj[NUM_GENES * DIM];   // 10.2 MB
__device__ float g_h[B_NODES * DIM];             //  2.0 MB
__device__ float g_agg[6 * B_NODES * DIM];       // 12.6 MB  [l*3+t][B][D]

// ---------------- f32x2 packed-FMA helpers (Blackwell) ----------------
__device__ __forceinline__ unsigned long long pack2(float x, float y) {
    unsigned long long r;
    asm("mov.b64 %0, {%1, %2};" : "=l"(r) : "f"(x), "f"(y));
    return r;
}
__device__ __forceinline__ void fma2(unsigned long long& d,
                                     unsigned long long a, unsigned long long b) {
    asm("fma.rn.f32x2 %0, %1, %2, %0;" : "+l"(d) : "l"(a), "l"(b));
}
__device__ __forceinline__ float2 unpack2(unsigned long long v) {
    float lo, hi;
    asm("mov.b64 {%0, %1}, %2;" : "=f"(lo), "=f"(hi) : "l"(v));
    return make_float2(lo, hi);
}

// ==================================================================
// Projection GEMM: out[M,128] = F[M,K] @ W[K,128] + bias
// BM=128, BN=128, BK=32, 256 threads.
// Per-thread: 8 rows (ty*8+i) x 8 cols (tx*2 + j*32) as 4 f32x2 pairs.
// Strided cols -> W LDS.64 covers all 32 banks conflict-free.
// ==================================================================
template <int K>
__global__ __launch_bounds__(256) void proj_kernel(
    const float* __restrict__ F, const float* __restrict__ W,
    const float* __restrict__ bias, float* __restrict__ out, int M)
{
    __shared__ float As[128 * 33];    // pitch 33: row-broadcast conflict-free
    __shared__ float Bs[32 * 128];

    const int tid  = threadIdx.x;
    const int tx   = tid & 15;        // 16 col groups
    const int ty   = tid >> 4;        // 16 row groups of 8
    const int row0 = blockIdx.x * 128;

    unsigned long long acc[8][4];
#pragma unroll
    for (int i = 0; i < 8; i++)
#pragma unroll
        for (int j = 0; j < 4; j++) acc[i][j] = 0ull;

    for (int kt = 0; kt < K / 32; kt++) {
        // A tile 128x32 (guarded), scalar stores into pitch-33 rows
#pragma unroll
        for (int i = 0; i < 4; i++) {
            int f  = tid + i * 256;               // 0..1023 float4s
            int r  = f >> 3;
            int c4 = f & 7;
            float4 v = make_float4(0.f, 0.f, 0.f, 0.f);
            if (row0 + r < M)
                v = *(const float4*)(F + (size_t)(row0 + r) * K + kt * 32 + c4 * 4);
            float* dst = As + r * 33 + c4 * 4;
            dst[0] = v.x; dst[1] = v.y; dst[2] = v.z; dst[3] = v.w;
        }
        // B tile 32x128
        const float4* wsrc = (const float4*)(W + (size_t)kt * 32 * 128);
#pragma unroll
        for (int i = 0; i < 4; i++)
            ((float4*)Bs)[tid + i * 256] = wsrc[tid + i * 256];
        __syncthreads();

#pragma unroll 4
        for (int k = 0; k < 32; k++) {
            unsigned long long ap[8];
#pragma unroll
            for (int i = 0; i < 8; i++) {
                float a = As[(ty * 8 + i) * 33 + k];
                ap[i] = pack2(a, a);
            }
            const unsigned long long* bp =
                (const unsigned long long*)(Bs + k * 128 + tx * 2);
#pragma unroll
            for (int j = 0; j < 4; j++) {
                unsigned long long bv = bp[j * 16];   // cols tx*2 + j*32
#pragma unroll
                for (int i = 0; i < 8; i++) fma2(acc[i][j], ap[i], bv);
            }
        }
        __syncthreads();
    }

#pragma unroll
    for (int i = 0; i < 8; i++) {
        int row = row0 + ty * 8 + i;
        if (row < M) {
#pragma unroll
            for (int j = 0; j < 4; j++) {
                int c = tx * 2 + j * 32;
                float2 v = unpack2(acc[i][j]);
                v.x += bias[c];
                v.y += bias[c + 1];
                *(float2*)(out + (size_t)row * 128 + c) = v;
            }
        }
    }
}

// ==================================================================
// Center embedding gather: h[b] = drug_proj[center_ids[b]]
// ==================================================================
__global__ void gather_center(const float* __restrict__ drug_proj,
                              const int* __restrict__ ids,
                              float* __restrict__ h)
{
    int i = blockIdx.x * blockDim.x + threadIdx.x;  // float4 index
    if (i < B_NODES * 32) {
        int r = i >> 5;
        int c = i & 31;
        ((float4*)h)[i] =
            ((const float4*)(drug_proj + (size_t)ids[r] * 128))[c];
    }
}

// ==================================================================
// Fused RNN aggregation: one block = 64 B-rows of one (layer,type).
// 256 threads (8 warps -> 2 warps/SMSP for latency hiding).
// Per-thread: 4 rows (ty*4+i) x 8 cols (tx*2 + j*32).
// Wx/Wh/bias resident in smem; H kept in smem across 10 steps.
// All smem access patterns conflict-free by construction:
//   - row broadcasts: rows differ by 4 -> 4*132 = 528 == 16 mod 32
//   - W LDS.64 at tx*2: 16 lanes cover banks 0..31 exactly once
// grid = (64, 6).
// ==================================================================
__global__ __launch_bounds__(256) void rnn_kernel(
    const float* __restrict__ cell_tab,
    const int*   __restrict__ cell_neigh,
    const int*   __restrict__ drug_neigh,
    const int*   __restrict__ gene_neigh,
    const float* __restrict__ rnn_Wx,
    const float* __restrict__ rnn_Wh,
    const float* __restrict__ rnn_b)
{
    extern __shared__ float sm[];
    float* Wx  = sm;                    // 16384
    float* Wh  = sm + 16384;            // 16384
    float* bsh = sm + 32768;            // 128
    float* Hs  = sm + 32896;            // 64*132
    float* Xs  = Hs + 64 * 132;         // 64*132

    const int tid   = threadIdx.x;
    const int tx    = tid & 15;
    const int ty    = tid >> 4;
    const int lt    = blockIdx.y;       // 0..5 = layer*3 + type
    const int layer = lt / 3;
    const int t     = lt % 3;
    const int row0  = blockIdx.x * 64;

    const float* table;
    const int*   neigh;
    if (t == 0)      { table = cell_tab;    neigh = cell_neigh; }
    else if (t == 1) { table = g_drug_proj; neigh = drug_neigh; }
    else             { table = g_gene_proj; neigh = gene_neigh; }

    // resident weights + bias
    {
        const float4* wx4 = (const float4*)(rnn_Wx + (size_t)lt * 16384);
        const float4* wh4 = (const float4*)(rnn_Wh + (size_t)lt * 16384);
        float4* dWx = (float4*)Wx;
        float4* dWh = (float4*)Wh;
#pragma unroll
        for (int i = 0; i < 16; i++) {
            dWx[tid + i * 256] = wx4[tid + i * 256];
            dWh[tid + i * 256] = wh4[tid + i * 256];
        }
        if (tid < 128) bsh[tid] = rnn_b[lt * 128 + tid];
    }
    for (int i = tid; i < 64 * 132; i += 256) Hs[i] = 0.f;

    for (int s = 0; s < S_SAMP; s++) {
        __syncthreads();
        // gather X tile: 64 rows x 128 cols = 2048 float4s
#pragma unroll
        for (int i = 0; i < 8; i++) {
            int f  = tid + i * 256;
            int r  = f >> 5;
            int c4 = f & 31;
            int nid = neigh[(layer * B_NODES + row0 + r) * S_SAMP + s];
            *(float4*)(Xs + r * 132 + c4 * 4) =
                *(const float4*)(table + (size_t)nid * 128 + c4 * 4);
        }
        __syncthreads();

        unsigned long long acc[4][4];
#pragma unroll
        for (int i = 0; i < 4; i++)
#pragma unroll
            for (int j = 0; j < 4; j++) acc[i][j] = 0ull;

#pragma unroll 4
        for (int k = 0; k < 128; k++) {
            unsigned long long px[4], ph[4];
#pragma unroll
            for (int i = 0; i < 4; i++) {
                float xv = Xs[(ty * 4 + i) * 132 + k];
                float hv = Hs[(ty * 4 + i) * 132 + k];
                px[i] = pack2(xv, xv);
                ph[i] = pack2(hv, hv);
            }
            const unsigned long long* bx =
                (const unsigned long long*)(Wx + k * 128 + tx * 2);
            const unsigned long long* bh =
                (const unsigned long long*)(Wh + k * 128 + tx * 2);
#pragma unroll
            for (int j = 0; j < 4; j++) {
                unsigned long long wxv = bx[j * 16];
                unsigned long long whv = bh[j * 16];
#pragma unroll
                for (int i = 0; i < 4; i++) {
                    fma2(acc[i][j], px[i], wxv);
                    fma2(acc[i][j], ph[i], whv);
                }
            }
        }
        __syncthreads();

        // h = tanh(acc + b)
#pragma unroll
        for (int i = 0; i < 4; i++) {
            int r = ty * 4 + i;
#pragma unroll
            for (int j = 0; j < 4; j++) {
                int c = tx * 2 + j * 32;
                float2 v = unpack2(acc[i][j]);
                float2 hv;
                hv.x = tanhf(v.x + bsh[c]);
                hv.y = tanhf(v.y + bsh[c + 1]);
                *(float2*)(Hs + r * 132 + c) = hv;
            }
        }
    }
    __syncthreads();

    // write agg
    float* out = g_agg + ((size_t)lt * B_NODES + row0) * 128;
    for (int i = tid; i < 64 * 128; i += 256) {
        int r = i >> 7;
        int c = i & 127;
        out[(size_t)r * 128 + c] = Hs[r * 132 + c];
    }
}

// ==================================================================
// Attention combine: warp per row. cands = [h, agg_cell, agg_drug, agg_gene]
// ==================================================================
__device__ __forceinline__ float warp_dot(float4 x, float4 y) {
    float v = x.x * y.x + x.y * y.y + x.z * y.z + x.w * y.w;
#pragma unroll
    for (int o = 16; o; o >>= 1) v += __shfl_xor_sync(0xffffffffu, v, o);
    return v;
}

__global__ void att_kernel(const float* __restrict__ hin,
                           const float* __restrict__ aggL,   // [3][B][128]
                           const float* __restrict__ attw,   // 256
                           float* __restrict__ out)
{
    int lane = threadIdx.x & 31;
    int w    = threadIdx.x >> 5;
    int row  = blockIdx.x * 4 + w;

    float4 hv = ((const float4*)(hin + (size_t)row * 128))[lane];
    float4 a0 = ((const float4*)(aggL + (size_t)row * 128))[lane];
    float4 a1 = ((const float4*)(aggL + (size_t)(B_NODES + row) * 128))[lane];
    float4 a2 = ((const float4*)(aggL + (size_t)(2 * B_NODES + row) * 128))[lane];
    float4 w1 = ((const float4*)attw)[lane];
    float4 w2 = ((const float4*)attw)[32 + lane];

    float ss = warp_dot(w1, hv);
    float sc[4];
    sc[0] = ss + warp_dot(w2, hv);
    sc[1] = ss + warp_dot(w2, a0);
    sc[2] = ss + warp_dot(w2, a1);
    sc[3] = ss + warp_dot(w2, a2);

#pragma unroll
    for (int c = 0; c < 4; c++)
        sc[c] = sc[c] > 0.f ? sc[c] : 0.01f * sc[c];   // leaky_relu(0.01)

    float m = fmaxf(fmaxf(sc[0], sc[1]), fmaxf(sc[2], sc[3]));
    float e0 = expf(sc[0] - m), e1 = expf(sc[1] - m);
    float e2 = expf(sc[2] - m), e3 = expf(sc[3] - m);
    float inv = 1.f / (e0 + e1 + e2 + e3);
    e0 *= inv; e1 *= inv; e2 *= inv; e3 *= inv;

    float4 o;
    o.x = e0 * hv.x + e1 * a0.x + e2 * a1.x + e3 * a2.x;
    o.y = e0 * hv.y + e1 * a0.y + e2 * a1.y + e3 * a2.y;
    o.z = e0 * hv.z + e1 * a0.z + e2 * a1.z + e3 * a2.z;
    o.w = e0 * hv.w + e1 * a0.w + e2 * a1.w + e3 * a2.w;
    ((float4*)(out + (size_t)row * 128))[lane] = o;
}

// ==================================================================
// Launch
// ==================================================================
extern "C" void kernel_launch(void* const* d_in, const int* in_sizes, int n_in,
                              void* d_out, int out_size)
{
    (void)in_sizes; (void)n_in; (void)out_size;

    const float* drug_feats = (const float*)d_in[0];
    const float* gene_feats = (const float*)d_in[1];
    const float* cell_tab   = (const float*)d_in[2];
    const float* W_drug     = (const float*)d_in[3];
    const float* b_drug     = (const float*)d_in[4];
    const float* W_gene     = (const float*)d_in[5];
    const float* b_gene     = (const float*)d_in[6];
    const float* rnn_Wx     = (const float*)d_in[7];
    const float* rnn_Wh     = (const float*)d_in[8];
    const float* rnn_b      = (const float*)d_in[9];
    const float* att_w      = (const float*)d_in[10];
    const int*   center_ids = (const int*)d_in[11];
    const int*   cell_neigh = (const int*)d_in[12];
    const int*   drug_neigh = (const int*)d_in[13];
    const int*   gene_neigh = (const int*)d_in[14];
    float*       out        = (float*)d_out;

    float *drug_proj, *gene_proj, *h, *agg;
    cudaGetSymbolAddress((void**)&drug_proj, g_drug_proj);
    cudaGetSymbolAddress((void**)&gene_proj, g_gene_proj);
    cudaGetSymbolAddress((void**)&h,         g_h);
    cudaGetSymbolAddress((void**)&agg,       g_agg);

    const size_t rnn_smem =
        (size_t)(16384 * 2 + 128 + 64 * 132 * 2) * sizeof(float);  // 199168 B
    cudaFuncSetAttribute(rnn_kernel,
                         cudaFuncAttributeMaxDynamicSharedMemorySize,
                         (int)rnn_smem);

    // 1) project full feature tables once (6x FLOP reduction vs per-sample)
    proj_kernel<1024><<<(NUM_DRUGS + 127) / 128, 256>>>(drug_feats, W_drug, b_drug,
                                                        drug_proj, NUM_DRUGS);
    proj_kernel<2048><<<(NUM_GENES + 127) / 128, 256>>>(gene_feats, W_gene, b_gene,
                                                        gene_proj, NUM_GENES);

    // 2) center embeddings
    gather_center<<<512, 256>>>(drug_proj, center_ids, h);

    // 3) all 6 (layer,type) RNN aggregations in one grid (h-independent)
    rnn_kernel<<<dim3(64, 6), 256, rnn_smem>>>(cell_tab, cell_neigh, drug_neigh,
                                               gene_neigh, rnn_Wx, rnn_Wh, rnn_b);

    // 4) attention combine per layer (layer 0 in-place on h, layer 1 -> out)
    att_kernel<<<B_NODES / 4, 128>>>(h, agg, att_w, h);
    att_kernel<<<B_NODES / 4, 128>>>(h, agg + (size_t)3 * B_NODES * DIM,
                                     att_w + 256, out);
}